// round 4
// baseline (speedup 1.0000x reference)
#include <cuda_runtime.h>
#include <cstdint>

// Problem shape (fixed by the dataset):
//   inp:[2048,2048,3] f32, w_ih:[96,3], w_hh:[96,32], bias:[96], bias_n:[32]
//   out:[2048,2048,1] f32  (h[0] at every step)
#define TT 2048
#define BB 2048

// Packed dual-FMA (sm_103a f32x2 path; ptxas never auto-fuses this).
__device__ __forceinline__ void ffma2(unsigned long long &d,
                                      unsigned long long a,
                                      unsigned long long b) {
    asm("fma.rn.f32x2 %0, %1, %2, %0;" : "+l"(d) : "l"(a), "l"(b));
}

__device__ __forceinline__ float2 unpack2(unsigned long long v) {
    float2 r;
    asm("mov.b64 {%0, %1}, %2;" : "=f"(r.x), "=f"(r.y) : "l"(v));
    return r;
}

// MUFU-based activations: EX2 + RCP, ~2-3 ulp — safe for 1e-3 over 2048 steps.
__device__ __forceinline__ float sigmoid_fast(float x) {
    return __fdividef(1.0f, 1.0f + __expf(-x));
}
__device__ __forceinline__ float tanh_fast2(float x) {
    return __fdividef(2.0f, 1.0f + __expf(-2.0f * x)) - 1.0f;
}

// One warp per sequence; lane j owns hidden unit j.
// W_hh rows for lane j (3 gates x 32) live in registers as 48 packed f32x2.
// h is broadcast lane->lane through a double-buffered smem vector read as u64
// pairs (feeds fma.rn.f32x2 with zero packing cost). One __syncwarp per step.
__global__ void __launch_bounds__(32, 14)
gru_warp_kernel(const float* __restrict__ inp,
                const float* __restrict__ w_ih,
                const float* __restrict__ w_hh,
                const float* __restrict__ bias,
                const float* __restrict__ bias_n,
                float* __restrict__ out) {
    __shared__ __align__(8) float hbuf[2][32];
    __shared__ float xbuf[96];  // 32 timesteps of x (3 floats each)

    const int j = threadIdx.x;   // hidden unit index 0..31
    const int b = blockIdx.x;    // sequence index

    // ---- load per-lane weights into registers (one-time) ----
    unsigned long long wr[16], wz[16], wa[16];
    {
        const unsigned long long* rr =
            reinterpret_cast<const unsigned long long*>(w_hh + (0 * 32 + j) * 32);
        const unsigned long long* rz =
            reinterpret_cast<const unsigned long long*>(w_hh + (1 * 32 + j) * 32);
        const unsigned long long* ra =
            reinterpret_cast<const unsigned long long*>(w_hh + (2 * 32 + j) * 32);
#pragma unroll
        for (int k = 0; k < 16; k++) { wr[k] = rr[k]; wz[k] = rz[k]; wa[k] = ra[k]; }
    }
    const float wir0 = w_ih[(0 * 32 + j) * 3 + 0];
    const float wir1 = w_ih[(0 * 32 + j) * 3 + 1];
    const float wir2 = w_ih[(0 * 32 + j) * 3 + 2];
    const float wiz0 = w_ih[(1 * 32 + j) * 3 + 0];
    const float wiz1 = w_ih[(1 * 32 + j) * 3 + 1];
    const float wiz2 = w_ih[(1 * 32 + j) * 3 + 2];
    const float wia0 = w_ih[(2 * 32 + j) * 3 + 0];
    const float wia1 = w_ih[(2 * 32 + j) * 3 + 1];
    const float wia2 = w_ih[(2 * 32 + j) * 3 + 2];
    const float br  = bias[0 * 32 + j];
    const float bz  = bias[1 * 32 + j];
    const float ban = bias[2 * 32 + j] + bias_n[j];  // fold bias_n in

    float h = 0.0f;
    const float* gx  = inp + (size_t)b * (TT * 3);
    float*       gout = out + (size_t)b * TT;

    for (int t = 0; t < TT; t++) {
        // Refill 32 timesteps of input cooperatively (coalesced, 3 LDG/lane).
        if ((t & 31) == 0) {
            __syncwarp();  // protect xbuf from stragglers of previous chunk
            const int base = t * 3;
            xbuf[j]      = gx[base + j];
            xbuf[32 + j] = gx[base + 32 + j];
            xbuf[64 + j] = gx[base + 64 + j];
        }

        // Publish h_t, then read whole vector back (broadcast LDS.64 pairs).
        hbuf[t & 1][j] = h;
        __syncwarp();

        const int ti = (t & 31) * 3;
        const float x0 = xbuf[ti + 0];
        const float x1 = xbuf[ti + 1];
        const float x2 = xbuf[ti + 2];
        const float ir = fmaf(wir2, x2, fmaf(wir1, x1, fmaf(wir0, x0, br)));
        const float iz = fmaf(wiz2, x2, fmaf(wiz1, x1, fmaf(wiz0, x0, bz)));
        const float ia = fmaf(wia2, x2, fmaf(wia1, x1, fmaf(wia0, x0, ban)));

        // Hidden matvec: 3 gates x 32 MACs as 48 dual FMAs.
        unsigned long long accr = 0ull, accz = 0ull, acca = 0ull;
        const unsigned long long* hp64 =
            reinterpret_cast<const unsigned long long*>(hbuf[t & 1]);
#pragma unroll
        for (int k = 0; k < 16; k++) {
            const unsigned long long hp = hp64[k];
            ffma2(accr, wr[k], hp);
            ffma2(accz, wz[k], hp);
            ffma2(acca, wa[k], hp);
        }
        const float2 fr = unpack2(accr);
        const float2 fz = unpack2(accz);
        const float2 fa = unpack2(acca);

        const float r = sigmoid_fast(ir + (fr.x + fr.y));
        const float z = sigmoid_fast(iz + (fz.x + fz.y));
        const float n = tanh_fast2(fmaf(r, fa.x + fa.y, ia));
        h = fmaf(z, h - n, n);   // (1-z)*n + z*h

        if (j == 0) gout[t] = h;
    }
}

extern "C" void kernel_launch(void* const* d_in, const int* in_sizes, int n_in,
                              void* d_out, int out_size) {
    const float* inp    = (const float*)d_in[0];
    const float* w_ih   = (const float*)d_in[1];
    const float* w_hh   = (const float*)d_in[2];
    const float* bias   = (const float*)d_in[3];
    const float* bias_n = (const float*)d_in[4];
    float* out = (float*)d_out;
    gru_warp_kernel<<<BB, 32>>>(inp, w_ih, w_hh, bias, bias_n, out);
}